// round 15
// baseline (speedup 1.0000x reference)
#include <cuda_runtime.h>
#include <cuda_fp16.h>
#include <cstdint>

typedef unsigned int u32;
typedef unsigned long long u64;

#define NN 2048
#define NE 6144
#define KDV 128
#define DVO 64
#define DEI 16
#define DEO 16

#define DV_SCALE (1.0f / 1024.0f)   // mult2 scale (fp16 range headroom)
#define HE_SCALE 4096.0f            // HeWsT pre-scale
#define HE_UNSCALE (1.0f / 4096.0f)

// =====================  scratch  =====================
__device__ __align__(16) __half g_m1A[NN * NE];         // fp16(T * d_e[col])
__device__ __align__(16) __half g_m1B[NN * NE];         // fp16(T)
__device__ __align__(16) __half g_m2B[NE * NN];         // fp16(T^T)  (A derived on the fly)
__device__ __align__(16) __half g_adjAvh[NN * NN];      // fp16 adjusted Av
__device__ __align__(16) __half g_adjAe[(size_t)NE * NE];   // fp16, scaled by 2^-10
__device__ __align__(16) float g_HW[NN * DVO];
__device__ __align__(16) __half g_HWhT[DVO * NN];       // fp16 HW^T
__device__ __align__(16) float g_hvp[4][NN * DVO];      // k_hv split-K partials
__device__ __align__(16) float g_HeW[NE * DEO];
__device__ __align__(16) __half g_HeWsT[DEO * NE];      // fp16 (HeW/colmax_s)^T * 2^12
__device__ __align__(16) float g_hep[4][NE * DEO];      // k_he split-K partials
__device__ __align__(16) float g_de[NE];
__device__ __align__(16) float g_dv[NN];
__device__ __align__(16) u32 g_dvh2[NN / 2];            // packed half2(dv*2^-10) pairs
__device__ u32 g_cmaxu[NE];

// =====================  helpers  =====================
__device__ __forceinline__ u32 smem_u32(const void* p) {
    u32 a;
    asm("{ .reg .u64 t; cvta.to.shared.u64 t, %1; cvt.u32.u64 %0, t; }" : "=r"(a) : "l"(p));
    return a;
}

__device__ __forceinline__ void cp16(u32 saddr, const __half* gptr) {
    asm volatile("cp.async.cg.shared.global [%0], [%1], 16;"
                 :: "r"(saddr), "l"(__cvta_generic_to_global(gptr)) : "memory");
}

#define LDSM4(r, addr)                                                          \
    asm volatile("ldmatrix.sync.aligned.m8n8.x4.shared.b16 {%0,%1,%2,%3}, [%4];" \
                 : "=r"((r)[0]), "=r"((r)[1]), "=r"((r)[2]), "=r"((r)[3]) : "r"(addr))

#define MMA_F16(d, a, b)                                                         \
    asm volatile("mma.sync.aligned.m16n8k16.row.col.f32.f16.f16.f32 "            \
                 "{%0,%1,%2,%3},{%4,%5,%6,%7},{%8,%9},{%0,%1,%2,%3};"            \
                 : "+f"((d)[0]), "+f"((d)[1]), "+f"((d)[2]), "+f"((d)[3])        \
                 : "r"((a)[0]), "r"((a)[1]), "r"((a)[2]), "r"((a)[3]),           \
                   "r"((b)[0]), "r"((b)[1]))

#define HMUL2U(d, a, b) \
    asm("mul.rn.f16x2 %0, %1, %2;" : "=r"(d) : "r"(a), "r"(b))

__device__ __forceinline__ u32 pkh2(__half a, __half b) {
    __half2 h = __halves2half2(a, b);
    return *(u32*)&h;
}
__device__ __forceinline__ u32 fkey(float f) {
    u32 b = __float_as_uint(f);
    return (b & 0x80000000u) ? ~b : (b | 0x80000000u);
}

// =====================  tiny prologue kernels  =====================
__global__ void k_de(const float* __restrict__ He, const float* __restrict__ pv) {
    int e = blockIdx.x * 256 + threadIdx.x;
    float s = 0.f;
#pragma unroll
    for (int k = 0; k < DEI; k++) s += He[e * DEI + k] * pv[k];
    g_de[e] = s;
    g_cmaxu[e] = 0u;            // fused colmax init
}

__global__ void k_hew(const float* __restrict__ He, const float* __restrict__ We) {
    int idx = blockIdx.x * 256 + threadIdx.x;
    int e = idx >> 4, c = idx & 15;
    float s = 0.f;
#pragma unroll
    for (int k = 0; k < DEI; k++) s += He[e * DEI + k] * We[k * DEO + c];
    g_HeW[idx] = s;
}

__global__ void k_hw(const float* __restrict__ Hv, const float* __restrict__ Wv) {
    int idx = blockIdx.x * 256 + threadIdx.x;
    int i = idx >> 6, c = idx & 63;
    float s = 0.f;
#pragma unroll 8
    for (int k = 0; k < KDV; k++) s += Hv[i * KDV + k] * Wv[k * DVO + c];
    g_HW[idx] = s;
}

// transpose HW -> fp16 HWhT[c][i]
__global__ void k_hwt() {
    __shared__ float t[64][65];
    const int r0 = blockIdx.x * 64;
    const int tid = threadIdx.x;
#pragma unroll
    for (int i = 0; i < 16; i++) {
        int id = tid + i * 256;
        int r = id >> 6, c = id & 63;
        t[r][c] = g_HW[(r0 + r) * DVO + c];
    }
    __syncthreads();
#pragma unroll
    for (int i = 0; i < 16; i++) {
        int id = tid + i * 256;
        int c = id >> 6, r = id & 63;
        g_HWhT[(size_t)c * NN + r0 + r] = __float2half_rn(t[r][c]);
    }
}

// mult1 prep: B = fp16(T), A = fp16(T * d_e[col]). [NN][NE] K-major.
__global__ void k_split1(const float* __restrict__ T) {
    size_t i = (size_t)blockIdx.x * 256 + threadIdx.x;   // float4 index
    float4 t = ((const float4*)T)[i];
    int col = (int)((i * 4) % NE);
    float4 de = *(const float4*)(g_de + col);
    ((uint2*)g_m1B)[i] = make_uint2(
        pkh2(__float2half_rn(t.x), __float2half_rn(t.y)),
        pkh2(__float2half_rn(t.z), __float2half_rn(t.w)));
    ((uint2*)g_m1A)[i] = make_uint2(
        pkh2(__float2half_rn(t.x * de.x), __float2half_rn(t.y * de.y)),
        pkh2(__float2half_rn(t.z * de.z), __float2half_rn(t.w * de.w)));
}

// mult2 prep (transpose): m2B[m][k] = fp16(T[k][m]) only (A derived in-kernel from d_v)
__global__ void k_split2(const float* __restrict__ T) {
    __shared__ float tile[64][33];
    const int m0 = blockIdx.x * 32, k0 = blockIdx.y * 64;
    const int tx = threadIdx.x, ty = threadIdx.y;     // (32, 8)
#pragma unroll
    for (int j = 0; j < 8; j++) {
        int r = ty + j * 8;
        tile[r][tx] = T[(size_t)(k0 + r) * NE + m0 + tx];
    }
    __syncthreads();
    const int lane = tx, w = ty;
#pragma unroll
    for (int q = 0; q < 4; q++) {
        const int mloc = w + 8 * q;
        const int m = m0 + mloc;
        float v0 = tile[2 * lane][mloc];
        float v1 = tile[2 * lane + 1][mloc];
        const size_t ob = ((size_t)m * NN + k0) >> 1;   // u32 index
        ((u32*)g_m2B)[ob + lane] = pkh2(__float2half_rn(v0), __float2half_rn(v1));
    }
}

// pack d_v pairs -> half2(dv * 2^-10)
__global__ void k_dvh() {
    int j = blockIdx.x * 256 + threadIdx.x;            // < 1024
    g_dvh2[j] = pkh2(__float2half_rn(g_dv[2 * j] * DV_SCALE),
                     __float2half_rn(g_dv[2 * j + 1] * DV_SCALE));
}

// =====================  fp16 1-term tensor-core GEMM, SYMMETRIC (triangular tiles)  ========
// which==0: M = m1A*m1B -> adjAvh fp16 (diag=1)
// which==1: M = (m2B . dv_k)*m2B -> adjAe fp16 scaled (diag=DV_SCALE) + colmax
#define KB 64
#define STG_BYTES 32768          // A 16K | B 16K
#define TP 129                   // transpose pitch (floats)
#define SMEM_DYN (128 * TP * 4 + 512)   // 66560 > 2*STG_BYTES = 65536

__device__ __forceinline__ void stage_load(u32 st0, int s,
        const __half* __restrict__ A, const __half* __restrict__ B,
        int K, int m0, int n0, int k0, int tid) {
    u32 base = st0 + s * STG_BYTES;
#pragma unroll
    for (int i = 0; i < 8; i++) {
        int id = tid + i * 128;                // 0..1023
        int r = id >> 3, c = id & 7;           // 128 rows x 8 16B-chunks
        u32 so = (u32)(r * 128 + ((c ^ (r & 7)) << 4));
        cp16(base + so, A + (size_t)(m0 + r) * K + k0 + c * 8);
        cp16(base + 16384 + so, B + (size_t)(n0 + r) * K + k0 + c * 8);
    }
    asm volatile("cp.async.commit_group;" ::: "memory");
}

__global__ __launch_bounds__(128, 2) void k_mult_mma(int which, const float* __restrict__ adj) {
    extern __shared__ char smem[];
    const __half *A, *B;
    int K, ncols;
    if (which == 0) { A = g_m1A; B = g_m1B; K = NE; ncols = NN; }
    else            { A = g_m2B; B = g_m2B; K = NN; ncols = NE; }
    // triangular tile decode: t -> (bi >= bj)
    const int t = blockIdx.x;
    int bi = (int)((sqrtf(8.0f * (float)t + 1.0f) - 1.0f) * 0.5f);
    while ((bi + 1) * (bi + 2) / 2 <= t) bi++;
    while (bi * (bi + 1) / 2 > t) bi--;
    const int bj = t - bi * (bi + 1) / 2;
    const int m0 = bi * 128, n0 = bj * 128;
    const bool diagtile = (bi == bj);

    const u32 st0 = smem_u32(smem);
    const int tid = threadIdx.x;
    const int lane = tid & 31, wid = tid >> 5;
    const int wm = wid >> 1, wn = wid & 1;          // 2 x 2 warp grid, 64x64 tiles
    const int nk = K / KB;

    float acc[4][8][4];
#pragma unroll
    for (int i = 0; i < 4; i++)
#pragma unroll
        for (int j = 0; j < 8; j++)
#pragma unroll
            for (int q = 0; q < 4; q++) acc[i][j][q] = 0.f;

    stage_load(st0, 0, A, B, K, m0, n0, 0, tid);
    stage_load(st0, 1, A, B, K, m0, n0, KB, tid);

    const u32 arow = (u32)(wm * 64 + (lane & 15));
    const u32 brow = (u32)(wn * 64 + (lane & 15));
    const u32 asw = arow & 7, bsw = brow & 7;

    for (int kt = 0; kt < nk; kt++) {
        const int s = kt & 1;
        if (kt + 1 < nk) asm volatile("cp.async.wait_group 1;" ::: "memory");
        else             asm volatile("cp.async.wait_group 0;" ::: "memory");
        __syncthreads();

        const u32 base = st0 + s * STG_BYTES;
#pragma unroll
        for (int ks = 0; ks < 4; ks++) {
            const u32 cb = (u32)(ks * 2) + (u32)(lane >> 4);
            u32 Bh[8][2], Ah[4][4];
            const u32 boff = base + 16384 + brow * 128 + ((cb ^ bsw) << 4);
#pragma unroll
            for (int nip = 0; nip < 4; nip++) {
                u32 tr[4];
                LDSM4(tr, boff + nip * 2048);
                Bh[2 * nip][0] = tr[0]; Bh[2 * nip][1] = tr[2];
                Bh[2 * nip + 1][0] = tr[1]; Bh[2 * nip + 1][1] = tr[3];
            }
            const u32 aoff = base + arow * 128 + ((cb ^ asw) << 4);
#pragma unroll
            for (int mi = 0; mi < 4; mi++)
                LDSM4(Ah[mi], aoff + mi * 2048);
            if (which == 1) {
                // on-the-fly A = B * dv[k]*2^-10 : regs {0,1} at k+0..1, {2,3} at k+8..9
                const int kk = kt * KB + ks * 16;
                const u32 dv01 = g_dvh2[(kk >> 1) + (lane & 3)];
                const u32 dv23 = g_dvh2[(kk >> 1) + 4 + (lane & 3)];
#pragma unroll
                for (int mi = 0; mi < 4; mi++) {
                    HMUL2U(Ah[mi][0], Ah[mi][0], dv01);
                    HMUL2U(Ah[mi][1], Ah[mi][1], dv01);
                    HMUL2U(Ah[mi][2], Ah[mi][2], dv23);
                    HMUL2U(Ah[mi][3], Ah[mi][3], dv23);
                }
            }
#pragma unroll
            for (int mi = 0; mi < 4; mi++)
#pragma unroll
                for (int ni = 0; ni < 8; ni++)
                    MMA_F16(acc[mi][ni], Ah[mi], Bh[ni]);
        }
        __syncthreads();
        if (kt + 2 < nk)
            stage_load(st0, s, A, B, K, m0, n0, (kt + 2) * KB, tid);
    }

    // ---------- epilogue ----------
    float* stg = (float*)smem;                         // 128 x TP floats (transpose staging)
    u32* scm = (u32*)(smem + 128 * TP * 4);            // 128 u32 colmax (direct block)
    if (which == 1 && tid < 128) scm[tid] = 0u;
    __syncthreads();

    u32 kmax[8][2];
#pragma unroll
    for (int ni = 0; ni < 8; ni++) { kmax[ni][0] = 0u; kmax[ni][1] = 0u; }

    const float dval = (which == 0) ? 1.0f : DV_SCALE;
    __half* C = (which == 0) ? g_adjAvh : g_adjAe;

#pragma unroll
    for (int mi = 0; mi < 4; mi++) {
#pragma unroll
        for (int h = 0; h < 2; h++) {
            const int row_l = wm * 64 + mi * 16 + (lane >> 2) + h * 8;
            const int row_g = m0 + row_l;
            const size_t rb = (size_t)row_g * ncols;
#pragma unroll
            for (int ni = 0; ni < 8; ni++) {
                const int col_l = wn * 64 + ni * 8 + (lane & 3) * 2;
                const int col_g = n0 + col_l;
                float v0 = acc[mi][ni][h * 2];
                float v1 = acc[mi][ni][h * 2 + 1];
                if (diagtile) {
                    if (row_g == col_g) v0 = dval;
                    if (row_g == col_g + 1) v1 = dval;
                } else {
                    stg[row_l * TP + col_l] = v0;
                    stg[row_l * TP + col_l + 1] = v1;
                }
                const float2 a = *(const float2*)(adj + rb + col_g);
                float w0 = v0 * a.x, w1 = v1 * a.y;
                *(__half2*)(C + rb + col_g) = __floats2half2_rn(w0, w1);
                if (which == 1) {
                    kmax[ni][0] = max(kmax[ni][0], fkey(w0));
                    kmax[ni][1] = max(kmax[ni][1], fkey(w1));
                }
            }
        }
    }
    if (which == 1) {
#pragma unroll
        for (int ni = 0; ni < 8; ni++) {
            const int cl = wn * 64 + ni * 8 + (lane & 3) * 2;
            atomicMax(scm + cl, kmax[ni][0]);
            atomicMax(scm + cl + 1, kmax[ni][1]);
        }
    }
    __syncthreads();
    if (which == 1 && tid < 128) atomicMax(g_cmaxu + n0 + tid, scm[tid]);

    // mirror block: C[n0+c][m0+r] = M[r][c] * adj[n0+c][m0+r]
    if (!diagtile) {
        u32 kloc[4] = {0u, 0u, 0u, 0u};
        for (int cc = 0; cc < 32; cc++) {
            const int c = wid * 32 + cc;
            const size_t orow = (size_t)(n0 + c) * ncols + m0;
#pragma unroll
            for (int ch = 0; ch < 4; ch++) {
                const int r = ch * 32 + lane;
                float v = stg[r * TP + c];
                float w = v * adj[orow + r];
                C[orow + r] = __float2half_rn(w);
                if (which == 1) kloc[ch] = max(kloc[ch], fkey(w));
            }
        }
        if (which == 1) {
#pragma unroll
            for (int ch = 0; ch < 4; ch++)
                atomicMax(g_cmaxu + m0 + ch * 32 + lane, kloc[ch]);
        }
    }
}

// =====================  Hv partials on tensor cores: g_hvp[kc] = adjAvh_chunk @ HWhT  ====
#define HV_KB 64
#define HV_STG 24576             // A 16K (128x128B) | B 8K (64x128B)
__global__ __launch_bounds__(128, 2) void k_hv_mma() {
    __shared__ __align__(1024) char smem[2 * HV_STG];
    const u32 st0 = smem_u32(smem);
    const int tid = threadIdx.x;
    const int lane = tid & 31, w = tid >> 5;
    const int m0 = blockIdx.x * 128;
    const int kc = blockIdx.y;
    const int kbase = kc * (NN / 4);                 // 512-wide K slice
    const int nk = (NN / 4) / HV_KB;                 // 8

    float acc[2][8][4];
#pragma unroll
    for (int i = 0; i < 2; i++)
#pragma unroll
        for (int j = 0; j < 8; j++)
#pragma unroll
            for (int q = 0; q < 4; q++) acc[i][j][q] = 0.f;

    auto load = [&](int s, int k0) {
        u32 base = st0 + s * HV_STG;
#pragma unroll
        for (int i = 0; i < 8; i++) {
            int id = tid + i * 128;
            int r = id >> 3, c = id & 7;
            u32 so = (u32)(r * 128 + ((c ^ (r & 7)) << 4));
            cp16(base + so, g_adjAvh + (size_t)(m0 + r) * NN + kbase + k0 + c * 8);
        }
#pragma unroll
        for (int i = 0; i < 4; i++) {
            int id = tid + i * 128;
            int r = id >> 3, c = id & 7;               // 64 rows x 8 chunks
            u32 so = (u32)(r * 128 + ((c ^ (r & 7)) << 4));
            cp16(base + 16384 + so, g_HWhT + (size_t)r * NN + kbase + k0 + c * 8);
        }
        asm volatile("cp.async.commit_group;" ::: "memory");
    };

    load(0, 0);
    load(1, HV_KB);

    const u32 arow = (u32)(w * 32 + (lane & 15));
    const u32 brow = (u32)(lane & 15);
    const u32 asw = arow & 7, bsw = brow & 7;

    for (int kt = 0; kt < nk; kt++) {
        const int s = kt & 1;
        if (kt + 1 < nk) asm volatile("cp.async.wait_group 1;" ::: "memory");
        else             asm volatile("cp.async.wait_group 0;" ::: "memory");
        __syncthreads();
        const u32 base = st0 + s * HV_STG;
#pragma unroll
        for (int ks = 0; ks < 4; ks++) {
            const u32 cb = (u32)(ks * 2) + (u32)(lane >> 4);
            u32 Bh[8][2], Af[2][4];
            const u32 boff = base + 16384 + brow * 128 + ((cb ^ bsw) << 4);
#pragma unroll
            for (int nip = 0; nip < 4; nip++) {
                u32 tr[4];
                LDSM4(tr, boff + nip * 2048);
                Bh[2 * nip][0] = tr[0]; Bh[2 * nip][1] = tr[2];
                Bh[2 * nip + 1][0] = tr[1]; Bh[2 * nip + 1][1] = tr[3];
            }
            const u32 aoff = base + arow * 128 + ((cb ^ asw) << 4);
            LDSM4(Af[0], aoff);
            LDSM4(Af[1], aoff + 2048);
#pragma unroll
            for (int mi = 0; mi < 2; mi++)
#pragma unroll
                for (int ni = 0; ni < 8; ni++)
                    MMA_F16(acc[mi][ni], Af[mi], Bh[ni]);
        }
        __syncthreads();
        if (kt + 2 < nk) load(s, (kt + 2) * HV_KB);
    }

#pragma unroll
    for (int mi = 0; mi < 2; mi++)
#pragma unroll
        for (int h = 0; h < 2; h++) {
            const int row_g = m0 + w * 32 + mi * 16 + (lane >> 2) + h * 8;
#pragma unroll
            for (int ni = 0; ni < 8; ni++) {
                const int col = ni * 8 + (lane & 3) * 2;
                *(float2*)(g_hvp[kc] + row_g * DVO + col) =
                    make_float2(acc[mi][ni][h * 2], acc[mi][ni][h * 2 + 1]);
            }
        }
}

// reduce Hv partials + bias -> out; fused d_v = Hv_out . p_e (one warp per row)
__global__ void k_hvdv(const float* __restrict__ bv, const float* __restrict__ pe,
                       float* __restrict__ out) {
    int w = (blockIdx.x * 256 + threadIdx.x) >> 5;     // row 0..2047
    int lane = threadIdx.x & 31;
    int i0 = w * DVO + lane, i1 = i0 + 32;
    float s0 = bv[lane] + g_hvp[0][i0] + g_hvp[1][i0] + g_hvp[2][i0] + g_hvp[3][i0];
    float s1 = bv[lane + 32] + g_hvp[0][i1] + g_hvp[1][i1] + g_hvp[2][i1] + g_hvp[3][i1];
    out[i0] = s0; out[i1] = s1;
    float d = s0 * pe[lane] + s1 * pe[lane + 32];
#pragma unroll
    for (int o = 16; o > 0; o >>= 1) d += __shfl_down_sync(0xffffffffu, d, o);
    if (lane == 0) g_dv[w] = d;
}

// finalize colmax; emit HeWsT[c][n] = fp16(HeW[n][c] / (colmax_s + 1e-10) * 2^12)
__global__ void k_cmax2() {
    int col = blockIdx.x * 256 + threadIdx.x;
    u32 k = g_cmaxu[col];
    u32 b = (k & 0x80000000u) ? (k ^ 0x80000000u) : ~k;
    float m = __uint_as_float(b);
    float inv = HE_SCALE / (m + 1e-10f);
#pragma unroll
    for (int c = 0; c < DEO; c++)
        g_HeWsT[c * NE + col] = __float2half_rn(g_HeW[col * DEO + c] * inv);
}

// =====================  He partials via tensor cores  ====
#define HE_KB 64
#define HE_STG 18432             // A 16K (128x128B) | B 2K (16x128B)
__global__ __launch_bounds__(128, 2) void k_he_mma() {
    __shared__ __align__(1024) char smem[2 * HE_STG];
    const u32 st0 = smem_u32(smem);
    const int tid = threadIdx.x;
    const int lane = tid & 31, w = tid >> 5;
    const int m0 = blockIdx.x * 128;
    const int kc = blockIdx.y;
    const int kbase = kc * (NE / 4);
    const int nk = (NE / 4) / HE_KB;                 // 24

    float acc[2][2][4];
#pragma unroll
    for (int i = 0; i < 2; i++)
#pragma unroll
        for (int j = 0; j < 2; j++)
#pragma unroll
            for (int q = 0; q < 4; q++) acc[i][j][q] = 0.f;

    auto load = [&](int s, int k0) {
        u32 base = st0 + s * HE_STG;
#pragma unroll
        for (int i = 0; i < 8; i++) {
            int id = tid + i * 128;
            int r = id >> 3, c = id & 7;
            u32 so = (u32)(r * 128 + ((c ^ (r & 7)) << 4));
            cp16(base + so, g_adjAe + (size_t)(m0 + r) * NE + kbase + k0 + c * 8);
        }
        {
            int r = tid >> 3, c = tid & 7;
            u32 so = (u32)(r * 128 + ((c ^ (r & 7)) << 4));
            cp16(base + 16384 + so, g_HeWsT + (size_t)r * NE + kbase + k0 + c * 8);
        }
        asm volatile("cp.async.commit_group;" ::: "memory");
    };

    load(0, 0);
    load(1, HE_KB);

    const u32 arow = (u32)(w * 32 + (lane & 15));
    const u32 brow = (u32)(lane & 15);
    const u32 asw = arow & 7, bsw = brow & 7;

    for (int kt = 0; kt < nk; kt++) {
        const int s = kt & 1;
        if (kt + 1 < nk) asm volatile("cp.async.wait_group 1;" ::: "memory");
        else             asm volatile("cp.async.wait_group 0;" ::: "memory");
        __syncthreads();
        const u32 base = st0 + s * HE_STG;
#pragma unroll
        for (int ks = 0; ks < 4; ks++) {
            const u32 cb = (u32)(ks * 2) + (u32)(lane >> 4);
            u32 Bf[2][2], Af[2][4];
            {
                u32 tr[4];
                LDSM4(tr, base + 16384 + brow * 128 + ((cb ^ bsw) << 4));
                Bf[0][0] = tr[0]; Bf[0][1] = tr[2];
                Bf[1][0] = tr[1]; Bf[1][1] = tr[3];
            }
            const u32 aoff = base + arow * 128 + ((cb ^ asw) << 4);
            LDSM4(Af[0], aoff);
            LDSM4(Af[1], aoff + 2048);
#pragma unroll
            for (int mi = 0; mi < 2; mi++)
#pragma unroll
                for (int ni = 0; ni < 2; ni++)
                    MMA_F16(acc[mi][ni], Af[mi], Bf[ni]);
        }
        __syncthreads();
        if (kt + 2 < nk) load(s, (kt + 2) * HE_KB);
    }

#pragma unroll
    for (int mi = 0; mi < 2; mi++)
#pragma unroll
        for (int h = 0; h < 2; h++) {
            const int row_g = m0 + w * 32 + mi * 16 + (lane >> 2) + h * 8;
#pragma unroll
            for (int ni = 0; ni < 2; ni++) {
                const int col = ni * 8 + (lane & 3) * 2;
                *(float2*)(g_hep[kc] + row_g * DEO + col) =
                    make_float2(acc[mi][ni][h * 2], acc[mi][ni][h * 2 + 1]);
            }
        }
}

// reduce He partials, unscale, + bias -> out
__global__ void k_hered(const float* __restrict__ be, float* __restrict__ out) {
    int idx = blockIdx.x * 256 + threadIdx.x;          // 98304
    int c = idx & 15;
    float s = (g_hep[0][idx] + g_hep[1][idx] + g_hep[2][idx] + g_hep[3][idx]) * HE_UNSCALE
              + be[c];
    out[idx] = s;
}

// =====================  launch  =====================
extern "C" void kernel_launch(void* const* d_in, const int* in_sizes, int n_in,
                              void* d_out, int out_size) {
    const float* H_v  = (const float*)d_in[0];
    const float* H_e  = (const float*)d_in[1];
    const float* adjv = (const float*)d_in[2];
    const float* adje = (const float*)d_in[3];
    const float* T    = (const float*)d_in[4];
    const float* W_v  = (const float*)d_in[5];
    const float* b_v  = (const float*)d_in[6];
    const float* p_v  = (const float*)d_in[7];
    const float* W_e  = (const float*)d_in[8];
    const float* b_e  = (const float*)d_in[9];
    const float* p_e  = (const float*)d_in[10];
    float* out = (float*)d_out;
    (void)in_sizes; (void)n_in; (void)out_size;

    cudaFuncSetAttribute(k_mult_mma, cudaFuncAttributeMaxDynamicSharedMemorySize, SMEM_DYN);

    k_de<<<24, 256>>>(H_e, p_v);                    // d_e + colmax init
    k_hew<<<384, 256>>>(H_e, W_e);
    k_hw<<<512, 256>>>(H_v, W_v);
    k_hwt<<<32, 256>>>();                           // HW -> fp16 HW^T
    k_split1<<<12288, 256>>>(T);
    k_split2<<<dim3(192, 32), dim3(32, 8)>>>(T);    // m2B only (no d_v needed)
    k_mult_mma<<<136, 128, SMEM_DYN>>>(0, adjv);    // adjAvh fp16, triangular
    k_hv_mma<<<dim3(16, 4), 128>>>();               // Hv partials on tensor cores
    k_hvdv<<<256, 256>>>(b_v, p_e, out);            // reduce + bias + d_v
    k_dvh<<<4, 256>>>();                            // pack dv half2
    k_mult_mma<<<1176, 128, SMEM_DYN>>>(1, adje);   // adjAe fp16 scaled + colmax (dv on the fly)
    k_cmax2<<<24, 256>>>();                         // colmax -> HeWsT fp16
    k_he_mma<<<dim3(48, 4), 128>>>();               // He partials on tensor cores
    k_hered<<<384, 256>>>(b_e, out + NN * DVO);     // reduce + unscale + bias
}

// round 17
// speedup vs baseline: 1.2075x; 1.2075x over previous
#include <cuda_runtime.h>
#include <cuda_fp16.h>
#include <cstdint>

typedef unsigned int u32;
typedef unsigned long long u64;

#define NN 2048
#define NE 6144
#define KDV 128
#define DVO 64
#define DEI 16
#define DEO 16

#define DV_SCALE (1.0f / 1024.0f)   // mult2 scale (fp16 range headroom)
#define HE_SCALE 4096.0f            // HeWsT pre-scale
#define HE_UNSCALE (1.0f / 4096.0f)

// =====================  scratch  =====================
__device__ __align__(16) __half g_m1A[NN * NE];         // fp16(T * d_e[col])
__device__ __align__(16) __half g_m1B[NN * NE];         // fp16(T)
__device__ __align__(16) __half g_m2A[NE * NN];         // fp16(T^T * d_v * 2^-10)
__device__ __align__(16) __half g_m2B[NE * NN];         // fp16(T^T)
__device__ __align__(16) __half g_adjAvh[NN * NN];      // fp16 adjusted Av
__device__ __align__(16) __half g_adjAe[(size_t)NE * NE];   // fp16, scaled by 2^-10
__device__ __align__(16) float g_HW[NN * DVO];
__device__ __align__(16) __half g_HWhT[DVO * NN];       // fp16 HW^T
__device__ __align__(16) float g_hvp[4][NN * DVO];      // k_hv split-K partials
__device__ __align__(16) float g_HeW[NE * DEO];
__device__ __align__(16) __half g_HeWsT[DEO * NE];      // fp16 (HeW/colmax_s)^T * 2^12
__device__ __align__(16) float g_hep[4][NE * DEO];      // k_he split-K partials
__device__ __align__(16) float g_de[NE];
__device__ __align__(16) float g_dv[NN];
__device__ u32 g_cmaxu[NE];

// =====================  helpers  =====================
__device__ __forceinline__ u32 smem_u32(const void* p) {
    u32 a;
    asm("{ .reg .u64 t; cvta.to.shared.u64 t, %1; cvt.u32.u64 %0, t; }" : "=r"(a) : "l"(p));
    return a;
}

__device__ __forceinline__ void cp16(u32 saddr, const __half* gptr) {
    asm volatile("cp.async.cg.shared.global [%0], [%1], 16;"
                 :: "r"(saddr), "l"(__cvta_generic_to_global(gptr)) : "memory");
}

#define LDSM4(r, addr)                                                          \
    asm volatile("ldmatrix.sync.aligned.m8n8.x4.shared.b16 {%0,%1,%2,%3}, [%4];" \
                 : "=r"((r)[0]), "=r"((r)[1]), "=r"((r)[2]), "=r"((r)[3]) : "r"(addr))

#define MMA_F16(d, a, b)                                                         \
    asm volatile("mma.sync.aligned.m16n8k16.row.col.f32.f16.f16.f32 "            \
                 "{%0,%1,%2,%3},{%4,%5,%6,%7},{%8,%9},{%0,%1,%2,%3};"            \
                 : "+f"((d)[0]), "+f"((d)[1]), "+f"((d)[2]), "+f"((d)[3])        \
                 : "r"((a)[0]), "r"((a)[1]), "r"((a)[2]), "r"((a)[3]),           \
                   "r"((b)[0]), "r"((b)[1]))

__device__ __forceinline__ u32 pkh2(__half a, __half b) {
    __half2 h = __halves2half2(a, b);
    return *(u32*)&h;
}
__device__ __forceinline__ u32 fkey(float f) {
    u32 b = __float_as_uint(f);
    return (b & 0x80000000u) ? ~b : (b | 0x80000000u);
}

// =====================  tiny prologue kernels  =====================
__global__ void k_de(const float* __restrict__ He, const float* __restrict__ pv) {
    int e = blockIdx.x * 256 + threadIdx.x;
    float s = 0.f;
#pragma unroll
    for (int k = 0; k < DEI; k++) s += He[e * DEI + k] * pv[k];
    g_de[e] = s;
    g_cmaxu[e] = 0u;            // fused colmax init
}

__global__ void k_hew(const float* __restrict__ He, const float* __restrict__ We) {
    int idx = blockIdx.x * 256 + threadIdx.x;
    int e = idx >> 4, c = idx & 15;
    float s = 0.f;
#pragma unroll
    for (int k = 0; k < DEI; k++) s += He[e * DEI + k] * We[k * DEO + c];
    g_HeW[idx] = s;
}

__global__ void k_hw(const float* __restrict__ Hv, const float* __restrict__ Wv) {
    int idx = blockIdx.x * 256 + threadIdx.x;
    int i = idx >> 6, c = idx & 63;
    float s = 0.f;
#pragma unroll 8
    for (int k = 0; k < KDV; k++) s += Hv[i * KDV + k] * Wv[k * DVO + c];
    g_HW[idx] = s;
}

// transpose HW -> fp16 HWhT[c][i]
__global__ void k_hwt() {
    __shared__ float t[64][65];
    const int r0 = blockIdx.x * 64;
    const int tid = threadIdx.x;
#pragma unroll
    for (int i = 0; i < 16; i++) {
        int id = tid + i * 256;
        int r = id >> 6, c = id & 63;
        t[r][c] = g_HW[(r0 + r) * DVO + c];
    }
    __syncthreads();
#pragma unroll
    for (int i = 0; i < 16; i++) {
        int id = tid + i * 256;
        int c = id >> 6, r = id & 63;
        g_HWhT[(size_t)c * NN + r0 + r] = __float2half_rn(t[r][c]);
    }
}

// mult1 prep: B = fp16(T), A = fp16(T * d_e[col]). [NN][NE] K-major.
__global__ void k_split1(const float* __restrict__ T) {
    size_t i = (size_t)blockIdx.x * 256 + threadIdx.x;   // float4 index
    float4 t = ((const float4*)T)[i];
    int col = (int)((i * 4) % NE);
    float4 de = *(const float4*)(g_de + col);
    ((uint2*)g_m1B)[i] = make_uint2(
        pkh2(__float2half_rn(t.x), __float2half_rn(t.y)),
        pkh2(__float2half_rn(t.z), __float2half_rn(t.w)));
    ((uint2*)g_m1A)[i] = make_uint2(
        pkh2(__float2half_rn(t.x * de.x), __float2half_rn(t.y * de.y)),
        pkh2(__float2half_rn(t.z * de.z), __float2half_rn(t.w * de.w)));
}

// mult2 prep (transpose): B2[m][k] = fp16(T[k][m]); A2[m][k] = fp16(T[k][m]*d_v[k]*2^-10).
__global__ void k_split2(const float* __restrict__ T) {
    __shared__ float tile[64][33];
    const int m0 = blockIdx.x * 32, k0 = blockIdx.y * 64;
    const int tx = threadIdx.x, ty = threadIdx.y;     // (32, 8)
#pragma unroll
    for (int j = 0; j < 8; j++) {
        int r = ty + j * 8;
        tile[r][tx] = T[(size_t)(k0 + r) * NE + m0 + tx];
    }
    __syncthreads();
    const int lane = tx, w = ty;
    float2 dv = ((const float2*)(g_dv + k0))[lane];
    dv.x *= DV_SCALE; dv.y *= DV_SCALE;
#pragma unroll
    for (int q = 0; q < 4; q++) {
        const int mloc = w + 8 * q;
        const int m = m0 + mloc;
        float v0 = tile[2 * lane][mloc];
        float v1 = tile[2 * lane + 1][mloc];
        const size_t ob = ((size_t)m * NN + k0) >> 1;   // u32 index
        ((u32*)g_m2B)[ob + lane] = pkh2(__float2half_rn(v0), __float2half_rn(v1));
        ((u32*)g_m2A)[ob + lane] =
            pkh2(__float2half_rn(v0 * dv.x), __float2half_rn(v1 * dv.y));
    }
}

// =====================  fp16 1-term tensor-core GEMM, SYMMETRIC (triangular tiles)  ========
// which==0: M = m1A*m1B -> adjAvh fp16 (diag=1)
// which==1: M = m2A*m2B -> adjAe fp16 scaled (diag=DV_SCALE) + colmax
#define KB 64
#define STG_BYTES 32768          // A 16K | B 16K
#define TP 129                   // transpose pitch (floats)
#define SMEM_DYN (128 * TP * 4 + 512)   // 66560 > 2*STG_BYTES = 65536

__device__ __forceinline__ void stage_load(u32 st0, int s,
        const __half* __restrict__ A, const __half* __restrict__ B,
        int K, int m0, int n0, int k0, int tid) {
    u32 base = st0 + s * STG_BYTES;
#pragma unroll
    for (int i = 0; i < 8; i++) {
        int id = tid + i * 128;                // 0..1023
        int r = id >> 3, c = id & 7;           // 128 rows x 8 16B-chunks
        u32 so = (u32)(r * 128 + ((c ^ (r & 7)) << 4));
        cp16(base + so, A + (size_t)(m0 + r) * K + k0 + c * 8);
        cp16(base + 16384 + so, B + (size_t)(n0 + r) * K + k0 + c * 8);
    }
    asm volatile("cp.async.commit_group;" ::: "memory");
}

__global__ __launch_bounds__(128, 2) void k_mult_mma(int which, const float* __restrict__ adj) {
    extern __shared__ char smem[];
    const __half *A, *B;
    int K, ncols;
    if (which == 0) { A = g_m1A; B = g_m1B; K = NE; ncols = NN; }
    else            { A = g_m2A; B = g_m2B; K = NN; ncols = NE; }
    // triangular tile decode: t -> (bi >= bj)
    const int t = blockIdx.x;
    int bi = (int)((sqrtf(8.0f * (float)t + 1.0f) - 1.0f) * 0.5f);
    while ((bi + 1) * (bi + 2) / 2 <= t) bi++;
    while (bi * (bi + 1) / 2 > t) bi--;
    const int bj = t - bi * (bi + 1) / 2;
    const int m0 = bi * 128, n0 = bj * 128;
    const bool diagtile = (bi == bj);

    const u32 st0 = smem_u32(smem);
    const int tid = threadIdx.x;
    const int lane = tid & 31, wid = tid >> 5;
    const int wm = wid >> 1, wn = wid & 1;          // 2 x 2 warp grid, 64x64 tiles
    const int nk = K / KB;

    float acc[4][8][4];
#pragma unroll
    for (int i = 0; i < 4; i++)
#pragma unroll
        for (int j = 0; j < 8; j++)
#pragma unroll
            for (int q = 0; q < 4; q++) acc[i][j][q] = 0.f;

    stage_load(st0, 0, A, B, K, m0, n0, 0, tid);
    stage_load(st0, 1, A, B, K, m0, n0, KB, tid);

    const u32 arow = (u32)(wm * 64 + (lane & 15));
    const u32 brow = (u32)(wn * 64 + (lane & 15));
    const u32 asw = arow & 7, bsw = brow & 7;

    for (int kt = 0; kt < nk; kt++) {
        const int s = kt & 1;
        if (kt + 1 < nk) asm volatile("cp.async.wait_group 1;" ::: "memory");
        else             asm volatile("cp.async.wait_group 0;" ::: "memory");
        __syncthreads();

        const u32 base = st0 + s * STG_BYTES;
#pragma unroll
        for (int ks = 0; ks < 4; ks++) {
            const u32 cb = (u32)(ks * 2) + (u32)(lane >> 4);
            u32 Bh[8][2], Ah[4][4];
            const u32 boff = base + 16384 + brow * 128 + ((cb ^ bsw) << 4);
#pragma unroll
            for (int nip = 0; nip < 4; nip++) {
                u32 tr[4];
                LDSM4(tr, boff + nip * 2048);
                Bh[2 * nip][0] = tr[0]; Bh[2 * nip][1] = tr[2];
                Bh[2 * nip + 1][0] = tr[1]; Bh[2 * nip + 1][1] = tr[3];
            }
            const u32 aoff = base + arow * 128 + ((cb ^ asw) << 4);
#pragma unroll
            for (int mi = 0; mi < 4; mi++)
                LDSM4(Ah[mi], aoff + mi * 2048);
#pragma unroll
            for (int mi = 0; mi < 4; mi++)
#pragma unroll
                for (int ni = 0; ni < 8; ni++)
                    MMA_F16(acc[mi][ni], Ah[mi], Bh[ni]);
        }
        __syncthreads();
        if (kt + 2 < nk)
            stage_load(st0, s, A, B, K, m0, n0, (kt + 2) * KB, tid);
    }

    // ---------- epilogue ----------
    float* stg = (float*)smem;                         // 128 x TP floats (transpose staging)
    u32* scm = (u32*)(smem + 128 * TP * 4);            // 128 u32 colmax (direct block)
    if (which == 1 && tid < 128) scm[tid] = 0u;
    __syncthreads();

    u32 kmax[8][2];
#pragma unroll
    for (int ni = 0; ni < 8; ni++) { kmax[ni][0] = 0u; kmax[ni][1] = 0u; }

    const float dval = (which == 0) ? 1.0f : DV_SCALE;
    __half* C = (which == 0) ? g_adjAvh : g_adjAe;

#pragma unroll
    for (int mi = 0; mi < 4; mi++) {
#pragma unroll
        for (int h = 0; h < 2; h++) {
            const int row_l = wm * 64 + mi * 16 + (lane >> 2) + h * 8;
            const int row_g = m0 + row_l;
            const size_t rb = (size_t)row_g * ncols;
#pragma unroll
            for (int ni = 0; ni < 8; ni++) {
                const int col_l = wn * 64 + ni * 8 + (lane & 3) * 2;
                const int col_g = n0 + col_l;
                float v0 = acc[mi][ni][h * 2];
                float v1 = acc[mi][ni][h * 2 + 1];
                if (diagtile) {
                    if (row_g == col_g) v0 = dval;
                    if (row_g == col_g + 1) v1 = dval;
                } else {
                    stg[row_l * TP + col_l] = v0;
                    stg[row_l * TP + col_l + 1] = v1;
                }
                const float2 a = *(const float2*)(adj + rb + col_g);
                float w0 = v0 * a.x, w1 = v1 * a.y;
                *(__half2*)(C + rb + col_g) = __floats2half2_rn(w0, w1);
                if (which == 1) {
                    kmax[ni][0] = max(kmax[ni][0], fkey(w0));
                    kmax[ni][1] = max(kmax[ni][1], fkey(w1));
                }
            }
        }
    }
    if (which == 1) {
#pragma unroll
        for (int ni = 0; ni < 8; ni++) {
            const int cl = wn * 64 + ni * 8 + (lane & 3) * 2;
            atomicMax(scm + cl, kmax[ni][0]);
            atomicMax(scm + cl + 1, kmax[ni][1]);
        }
    }
    __syncthreads();
    if (which == 1 && tid < 128) atomicMax(g_cmaxu + n0 + tid, scm[tid]);

    // mirror block: C[n0+c][m0+r] = M[r][c] * adj[n0+c][m0+r]
    if (!diagtile) {
        u32 kloc[4] = {0u, 0u, 0u, 0u};
        for (int cc = 0; cc < 32; cc++) {
            const int c = wid * 32 + cc;
            const size_t orow = (size_t)(n0 + c) * ncols + m0;
#pragma unroll
            for (int ch = 0; ch < 4; ch++) {
                const int r = ch * 32 + lane;
                float v = stg[r * TP + c];
                float w = v * adj[orow + r];
                C[orow + r] = __float2half_rn(w);
                if (which == 1) kloc[ch] = max(kloc[ch], fkey(w));
            }
        }
        if (which == 1) {
#pragma unroll
            for (int ch = 0; ch < 4; ch++)
                atomicMax(g_cmaxu + m0 + ch * 32 + lane, kloc[ch]);
        }
    }
}

// =====================  Hv partials on tensor cores: g_hvp[kc] = adjAvh_chunk @ HWhT  ====
#define HV_KB 64
#define HV_STG 24576             // A 16K (128x128B) | B 8K (64x128B)
__global__ __launch_bounds__(128, 2) void k_hv_mma() {
    __shared__ __align__(1024) char smem[2 * HV_STG];
    const u32 st0 = smem_u32(smem);
    const int tid = threadIdx.x;
    const int lane = tid & 31, w = tid >> 5;
    const int m0 = blockIdx.x * 128;
    const int kc = blockIdx.y;
    const int kbase = kc * (NN / 4);                 // 512-wide K slice
    const int nk = (NN / 4) / HV_KB;                 // 8

    float acc[2][8][4];
#pragma unroll
    for (int i = 0; i < 2; i++)
#pragma unroll
        for (int j = 0; j < 8; j++)
#pragma unroll
            for (int q = 0; q < 4; q++) acc[i][j][q] = 0.f;

    auto load = [&](int s, int k0) {
        u32 base = st0 + s * HV_STG;
#pragma unroll
        for (int i = 0; i < 8; i++) {
            int id = tid + i * 128;
            int r = id >> 3, c = id & 7;
            u32 so = (u32)(r * 128 + ((c ^ (r & 7)) << 4));
            cp16(base + so, g_adjAvh + (size_t)(m0 + r) * NN + kbase + k0 + c * 8);
        }
#pragma unroll
        for (int i = 0; i < 4; i++) {
            int id = tid + i * 128;
            int r = id >> 3, c = id & 7;               // 64 rows x 8 chunks
            u32 so = (u32)(r * 128 + ((c ^ (r & 7)) << 4));
            cp16(base + 16384 + so, g_HWhT + (size_t)r * NN + kbase + k0 + c * 8);
        }
        asm volatile("cp.async.commit_group;" ::: "memory");
    };

    load(0, 0);
    load(1, HV_KB);

    const u32 arow = (u32)(w * 32 + (lane & 15));
    const u32 brow = (u32)(lane & 15);
    const u32 asw = arow & 7, bsw = brow & 7;

    for (int kt = 0; kt < nk; kt++) {
        const int s = kt & 1;
        if (kt + 1 < nk) asm volatile("cp.async.wait_group 1;" ::: "memory");
        else             asm volatile("cp.async.wait_group 0;" ::: "memory");
        __syncthreads();
        const u32 base = st0 + s * HV_STG;
#pragma unroll
        for (int ks = 0; ks < 4; ks++) {
            const u32 cb = (u32)(ks * 2) + (u32)(lane >> 4);
            u32 Bh[8][2], Af[2][4];
            const u32 boff = base + 16384 + brow * 128 + ((cb ^ bsw) << 4);
#pragma unroll
            for (int nip = 0; nip < 4; nip++) {
                u32 tr[4];
                LDSM4(tr, boff + nip * 2048);
                Bh[2 * nip][0] = tr[0]; Bh[2 * nip][1] = tr[2];
                Bh[2 * nip + 1][0] = tr[1]; Bh[2 * nip + 1][1] = tr[3];
            }
            const u32 aoff = base + arow * 128 + ((cb ^ asw) << 4);
            LDSM4(Af[0], aoff);
            LDSM4(Af[1], aoff + 2048);
#pragma unroll
            for (int mi = 0; mi < 2; mi++)
#pragma unroll
                for (int ni = 0; ni < 8; ni++)
                    MMA_F16(acc[mi][ni], Af[mi], Bh[ni]);
        }
        __syncthreads();
        if (kt + 2 < nk) load(s, (kt + 2) * HV_KB);
    }

#pragma unroll
    for (int mi = 0; mi < 2; mi++)
#pragma unroll
        for (int h = 0; h < 2; h++) {
            const int row_g = m0 + w * 32 + mi * 16 + (lane >> 2) + h * 8;
#pragma unroll
            for (int ni = 0; ni < 8; ni++) {
                const int col = ni * 8 + (lane & 3) * 2;
                *(float2*)(g_hvp[kc] + row_g * DVO + col) =
                    make_float2(acc[mi][ni][h * 2], acc[mi][ni][h * 2 + 1]);
            }
        }
}

// reduce Hv partials + bias -> out; fused d_v = Hv_out . p_e (one warp per row)
__global__ void k_hvdv(const float* __restrict__ bv, const float* __restrict__ pe,
                       float* __restrict__ out) {
    int w = (blockIdx.x * 256 + threadIdx.x) >> 5;     // row 0..2047
    int lane = threadIdx.x & 31;
    int i0 = w * DVO + lane, i1 = i0 + 32;
    float s0 = bv[lane] + g_hvp[0][i0] + g_hvp[1][i0] + g_hvp[2][i0] + g_hvp[3][i0];
    float s1 = bv[lane + 32] + g_hvp[0][i1] + g_hvp[1][i1] + g_hvp[2][i1] + g_hvp[3][i1];
    out[i0] = s0; out[i1] = s1;
    float d = s0 * pe[lane] + s1 * pe[lane + 32];
#pragma unroll
    for (int o = 16; o > 0; o >>= 1) d += __shfl_down_sync(0xffffffffu, d, o);
    if (lane == 0) g_dv[w] = d;
}

// finalize colmax; emit HeWsT[c][n] = fp16(HeW[n][c] / (colmax_s + 1e-10) * 2^12)
__global__ void k_cmax2() {
    int col = blockIdx.x * 256 + threadIdx.x;
    u32 k = g_cmaxu[col];
    u32 b = (k & 0x80000000u) ? (k ^ 0x80000000u) : ~k;
    float m = __uint_as_float(b);
    float inv = HE_SCALE / (m + 1e-10f);
#pragma unroll
    for (int c = 0; c < DEO; c++)
        g_HeWsT[c * NE + col] = __float2half_rn(g_HeW[col * DEO + c] * inv);
}

// =====================  He partials via tensor cores  ====
#define HE_KB 64
#define HE_STG 18432             // A 16K (128x128B) | B 2K (16x128B)
__global__ __launch_bounds__(128, 2) void k_he_mma() {
    __shared__ __align__(1024) char smem[2 * HE_STG];
    const u32 st0 = smem_u32(smem);
    const int tid = threadIdx.x;
    const int lane = tid & 31, w = tid >> 5;
    const int m0 = blockIdx.x * 128;
    const int kc = blockIdx.y;
    const int kbase = kc * (NE / 4);
    const int nk = (NE / 4) / HE_KB;                 // 24

    float acc[2][2][4];
#pragma unroll
    for (int i = 0; i < 2; i++)
#pragma unroll
        for (int j = 0; j < 2; j++)
#pragma unroll
            for (int q = 0; q < 4; q++) acc[i][j][q] = 0.f;

    auto load = [&](int s, int k0) {
        u32 base = st0 + s * HE_STG;
#pragma unroll
        for (int i = 0; i < 8; i++) {
            int id = tid + i * 128;
            int r = id >> 3, c = id & 7;
            u32 so = (u32)(r * 128 + ((c ^ (r & 7)) << 4));
            cp16(base + so, g_adjAe + (size_t)(m0 + r) * NE + kbase + k0 + c * 8);
        }
        {
            int r = tid >> 3, c = tid & 7;
            u32 so = (u32)(r * 128 + ((c ^ (r & 7)) << 4));
            cp16(base + 16384 + so, g_HeWsT + (size_t)r * NE + kbase + k0 + c * 8);
        }
        asm volatile("cp.async.commit_group;" ::: "memory");
    };

    load(0, 0);
    load(1, HE_KB);

    const u32 arow = (u32)(w * 32 + (lane & 15));
    const u32 brow = (u32)(lane & 15);
    const u32 asw = arow & 7, bsw = brow & 7;

    for (int kt = 0; kt < nk; kt++) {
        const int s = kt & 1;
        if (kt + 1 < nk) asm volatile("cp.async.wait_group 1;" ::: "memory");
        else             asm volatile("cp.async.wait_group 0;" ::: "memory");
        __syncthreads();
        const u32 base = st0 + s * HE_STG;
#pragma unroll
        for (int ks = 0; ks < 4; ks++) {
            const u32 cb = (u32)(ks * 2) + (u32)(lane >> 4);
            u32 Bf[2][2], Af[2][4];
            {
                u32 tr[4];
                LDSM4(tr, base + 16384 + brow * 128 + ((cb ^ bsw) << 4));
                Bf[0][0] = tr[0]; Bf[0][1] = tr[2];
                Bf[1][0] = tr[1]; Bf[1][1] = tr[3];
            }
            const u32 aoff = base + arow * 128 + ((cb ^ asw) << 4);
            LDSM4(Af[0], aoff);
            LDSM4(Af[1], aoff + 2048);
#pragma unroll
            for (int mi = 0; mi < 2; mi++)
#pragma unroll
                for (int ni = 0; ni < 2; ni++)
                    MMA_F16(acc[mi][ni], Af[mi], Bf[ni]);
        }
        __syncthreads();
        if (kt + 2 < nk) load(s, (kt + 2) * HE_KB);
    }

#pragma unroll
    for (int mi = 0; mi < 2; mi++)
#pragma unroll
        for (int h = 0; h < 2; h++) {
            const int row_g = m0 + w * 32 + mi * 16 + (lane >> 2) + h * 8;
#pragma unroll
            for (int ni = 0; ni < 2; ni++) {
                const int col = ni * 8 + (lane & 3) * 2;
                *(float2*)(g_hep[kc] + row_g * DEO + col) =
                    make_float2(acc[mi][ni][h * 2], acc[mi][ni][h * 2 + 1]);
            }
        }
}

// reduce He partials, unscale, + bias -> out
__global__ void k_hered(const float* __restrict__ be, float* __restrict__ out) {
    int idx = blockIdx.x * 256 + threadIdx.x;          // 98304
    int c = idx & 15;
    float s = (g_hep[0][idx] + g_hep[1][idx] + g_hep[2][idx] + g_hep[3][idx]) * HE_UNSCALE
              + be[c];
    out[idx] = s;
}

// =====================  launch  =====================
extern "C" void kernel_launch(void* const* d_in, const int* in_sizes, int n_in,
                              void* d_out, int out_size) {
    const float* H_v  = (const float*)d_in[0];
    const float* H_e  = (const float*)d_in[1];
    const float* adjv = (const float*)d_in[2];
    const float* adje = (const float*)d_in[3];
    const float* T    = (const float*)d_in[4];
    const float* W_v  = (const float*)d_in[5];
    const float* b_v  = (const float*)d_in[6];
    const float* p_v  = (const float*)d_in[7];
    const float* W_e  = (const float*)d_in[8];
    const float* b_e  = (const float*)d_in[9];
    const float* p_e  = (const float*)d_in[10];
    float* out = (float*)d_out;
    (void)in_sizes; (void)n_in; (void)out_size;

    cudaFuncSetAttribute(k_mult_mma, cudaFuncAttributeMaxDynamicSharedMemorySize, SMEM_DYN);

    k_de<<<24, 256>>>(H_e, p_v);                    // d_e + colmax init
    k_hew<<<384, 256>>>(H_e, W_e);
    k_hw<<<512, 256>>>(H_v, W_v);
    k_hwt<<<32, 256>>>();                           // HW -> fp16 HW^T
    k_split1<<<12288, 256>>>(T);
    k_mult_mma<<<136, 128, SMEM_DYN>>>(0, adjv);    // adjAvh fp16, triangular
    k_hv_mma<<<dim3(16, 4), 128>>>();               // Hv partials on tensor cores
    k_hvdv<<<256, 256>>>(b_v, p_e, out);            // reduce + bias + d_v
    k_split2<<<dim3(192, 32), dim3(32, 8)>>>(T);    // m2A (precomputed dv) + m2B
    k_mult_mma<<<1176, 128, SMEM_DYN>>>(1, adje);   // adjAe fp16 scaled + colmax
    k_cmax2<<<24, 256>>>();                         // colmax -> HeWsT fp16
    k_he_mma<<<dim3(48, 4), 128>>>();               // He partials on tensor cores
    k_hered<<<384, 256>>>(b_e, out + NN * DVO);     // reduce + unscale + bias
}